// round 2
// baseline (speedup 1.0000x reference)
#include <cuda_runtime.h>
#include <math.h>

// Problem constants (fixed by the reference)
#define B_  64
#define S_  8192
#define H_  512
#define STILE 256
#define NTILES (S_ / STILE)    // 32
#define NBLOCKS1 (B_ * NTILES) // 2048

// Scratch (allocation-free: __device__ globals)
__device__ float g_partial[B_ * NTILES * H_];  // 4 MB: per-tile partial context
__device__ float g_m[B_ * NTILES];             // per-tile local max
__device__ float g_l[B_ * NTILES];             // per-tile local sumexp
__device__ float g_M[B_];                      // per-batch global max
__device__ float g_invT[B_];                   // per-batch 1/sumexp
__device__ int   g_mask_is_byte;               // mask dtype flag (detected)

// ---------------------------------------------------------------------------
// Kernel 0: detect mask element width. Safe read span under EITHER layout is
// B*S/4 uint32 words. If stored as 1-byte bools, a word >1 appears whenever
// any of bytes 1..3 is set (prob 7/8 per word over 131072 words -> certain).
// If stored as int32 bools, every word is 0 or 1.
// ---------------------------------------------------------------------------
__global__ void k0_detect_mask(const unsigned int* __restrict__ mw)
{
    __shared__ int found[256];
    const int tid = threadIdx.x;
    const int NW = (B_ * S_) / 4;   // 131072 words, safe under both layouts
    int f = 0;
    for (int i = tid; i < NW; i += 256)
        if (mw[i] > 1u) { f = 1; break; }
    found[tid] = f;
    __syncthreads();
    for (int off = 128; off; off >>= 1) {
        if (tid < off) found[tid] |= found[tid + off];
        __syncthreads();
    }
    if (tid == 0) g_mask_is_byte = found[0];
}

// ---------------------------------------------------------------------------
// Kernel 1: one block per (batch, S-tile). Each warp does online softmax +
// context accumulation for its strided subset of rows, fully in registers.
// Masked rows are skipped WITHOUT loading the 2KB encoder row (halves HBM).
// Raw scores (or -inf) are written into the weights region of d_out.
// ---------------------------------------------------------------------------
__global__ __launch_bounds__(256, 4)
void k1_scores_partials(const float* __restrict__ hid,
                        const float* __restrict__ enc,
                        const void* __restrict__ mask,
                        float* __restrict__ scores_out /* = d_out + B*H */)
{
    const int b = blockIdx.x / NTILES;
    const int t = blockIdx.x % NTILES;
    const int tid  = threadIdx.x;
    const int warp = tid >> 5;
    const int lane = tid & 31;

    __shared__ float4 sh_hid[H_ / 4];              // 2 KB
    __shared__ float  sm_ctx[8][H_];               // 16 KB
    __shared__ float  sm_m[8], sm_l[8];

    const int mask_is_byte = g_mask_is_byte;       // uniform
    const unsigned char* mrow8  = (const unsigned char*)mask + (size_t)b * S_ + t * STILE;
    const int*           mrow32 = (const int*)mask + (size_t)b * S_ + t * STILE;

    // load decoder_hidden[b,:] into smem (vectorized)
    {
        const float4* h4 = (const float4*)(hid + (size_t)b * H_);
        for (int i = tid; i < H_ / 4; i += 256) sh_hid[i] = h4[i];
    }
    __syncthreads();

    // each lane caches its 4 float4 chunks of hidden: h = 4*(lane + 32*j)
    float4 hv[4];
#pragma unroll
    for (int j = 0; j < 4; ++j) hv[j] = sh_hid[lane + 32 * j];

    float4 acc[4];
#pragma unroll
    for (int j = 0; j < 4; ++j) acc[j] = make_float4(0.f, 0.f, 0.f, 0.f);
    float m = -INFINITY;
    float lsum = 0.f;

    for (int r = warp; r < STILE; r += 8) {
        const int s = t * STILE + r;
        const bool keep = mask_is_byte ? (mrow8[r] != 0) : (mrow32[r] != 0);
        if (!keep) {
            if (lane == 0) scores_out[(size_t)b * S_ + s] = -INFINITY;
            continue;
        }
        const float4* row = (const float4*)(enc + ((size_t)b * S_ + s) * H_);
        float4 v[4];
        float p = 0.f;
#pragma unroll
        for (int j = 0; j < 4; ++j) {
            v[j] = row[lane + 32 * j];
            p += v[j].x * hv[j].x + v[j].y * hv[j].y
               + v[j].z * hv[j].z + v[j].w * hv[j].w;
        }
        // warp-reduce the dot product
#pragma unroll
        for (int off = 16; off; off >>= 1)
            p += __shfl_xor_sync(0xffffffffu, p, off);
        const float score = p;   // all lanes hold it
        if (lane == 0) scores_out[(size_t)b * S_ + s] = score;

        // online softmax update
        const float mn    = fmaxf(m, score);
        const float scale = __expf(m - mn);      // exp(-inf - finite) = 0 ok
        const float e     = __expf(score - mn);
        m = mn;
        lsum = lsum * scale + e;
#pragma unroll
        for (int j = 0; j < 4; ++j) {
            acc[j].x = acc[j].x * scale + e * v[j].x;
            acc[j].y = acc[j].y * scale + e * v[j].y;
            acc[j].z = acc[j].z * scale + e * v[j].z;
            acc[j].w = acc[j].w * scale + e * v[j].w;
        }
    }

    if (lane == 0) { sm_m[warp] = m; sm_l[warp] = lsum; }
    __syncthreads();

    // block max over the 8 warps
    float Mblk = -INFINITY;
#pragma unroll
    for (int w = 0; w < 8; ++w) Mblk = fmaxf(Mblk, sm_m[w]);

    // scale this warp's accumulator to the block max, dump to smem
    const float wm = sm_m[warp];
    const float wscale = (wm > -INFINITY) ? __expf(wm - Mblk) : 0.f;
    float4* dst = (float4*)sm_ctx[warp];
#pragma unroll
    for (int j = 0; j < 4; ++j) {
        float4 a = acc[j];
        a.x *= wscale; a.y *= wscale; a.z *= wscale; a.w *= wscale;
        dst[lane + 32 * j] = a;
    }
    __syncthreads();

    // reduce 8 warps -> per-tile partial context
    float* part = g_partial + ((size_t)(b * NTILES + t)) * H_;
    for (int h = tid; h < H_; h += 256) {
        float c = 0.f;
#pragma unroll
        for (int w = 0; w < 8; ++w) c += sm_ctx[w][h];
        part[h] = c;
    }

    if (tid == 0) {
        float L = 0.f;
#pragma unroll
        for (int w = 0; w < 8; ++w) {
            const float sc = (sm_m[w] > -INFINITY) ? __expf(sm_m[w] - Mblk) : 0.f;
            L += sm_l[w] * sc;
        }
        g_m[b * NTILES + t] = Mblk;
        g_l[b * NTILES + t] = L;
    }
}

// ---------------------------------------------------------------------------
// Kernel 2: one block per batch. Combine 32 tile partials -> context, and
// produce per-batch (M, 1/T) for the weights pass.
// ---------------------------------------------------------------------------
__global__ __launch_bounds__(256)
void k2_combine(float* __restrict__ ctx_out /* = d_out */)
{
    const int b   = blockIdx.x;
    const int tid = threadIdx.x;

    __shared__ float sc[NTILES];
    __shared__ float sh_M, sh_invT;

    if (tid == 0) {
        float Mb = -INFINITY;
        for (int t = 0; t < NTILES; ++t) Mb = fmaxf(Mb, g_m[b * NTILES + t]);
        sh_M = Mb;
    }
    __syncthreads();
    const float Mb = sh_M;

    if (tid < NTILES) {
        const float mt = g_m[b * NTILES + tid];
        sc[tid] = (mt > -INFINITY) ? __expf(mt - Mb) : 0.f;
    }
    __syncthreads();

    if (tid == 0) {
        float T = 0.f;
        for (int t = 0; t < NTILES; ++t) T += g_l[b * NTILES + t] * sc[t];
        const float invT = 1.f / T;
        sh_invT = invT;
        g_M[b] = Mb;
        g_invT[b] = invT;
    }
    __syncthreads();
    const float invT = sh_invT;

    for (int h = tid; h < H_; h += 256) {
        float c = 0.f;
#pragma unroll
        for (int t = 0; t < NTILES; ++t)
            c += g_partial[((size_t)(b * NTILES + t)) * H_ + h] * sc[t];
        ctx_out[(size_t)b * H_ + h] = c * invT;
    }
}

// ---------------------------------------------------------------------------
// Kernel 3: finalize weights in place: w = exp(score - M_b) * invT_b
// ---------------------------------------------------------------------------
__global__ __launch_bounds__(256)
void k3_weights(float* __restrict__ scores /* = d_out + B*S offset */)
{
    const int idx = blockIdx.x * 256 + threadIdx.x;
    if (idx >= B_ * S_) return;
    const int b = idx / S_;
    const float sc = scores[idx];
    scores[idx] = __expf(sc - g_M[b]) * g_invT[b];
}

// ---------------------------------------------------------------------------
extern "C" void kernel_launch(void* const* d_in, const int* in_sizes, int n_in,
                              void* d_out, int out_size)
{
    const float* hid  = (const float*)d_in[0];   // [B,H]
    const float* enc  = (const float*)d_in[1];   // [B,S,H]
    const void*  mask = d_in[2];                 // [B,S] bool (width detected)

    float* ctx     = (float*)d_out;            // [B,H]
    float* weights = (float*)d_out + B_ * H_;  // [B,S]

    k0_detect_mask<<<1, 256>>>((const unsigned int*)mask);
    k1_scores_partials<<<NBLOCKS1, 256>>>(hid, enc, mask, weights);
    k2_combine<<<B_, 256>>>(ctx);
    k3_weights<<<(B_ * S_ + 255) / 256, 256>>>(weights);
}

// round 3
// speedup vs baseline: 2.6139x; 2.6139x over previous
#include <cuda_runtime.h>
#include <math.h>

// Problem constants (fixed by the reference)
#define B_  64
#define S_  8192
#define H_  512
#define STILE 256
#define NTILES (S_ / STILE)    // 32
#define NBLOCKS1 (B_ * NTILES) // 2048

// Scratch (allocation-free: __device__ globals)
__device__ float g_partial[B_ * NTILES * H_];  // 4 MB: per-tile partial context
__device__ float g_m[B_ * NTILES];             // per-tile local max
__device__ float g_l[B_ * NTILES];             // per-tile local sumexp
__device__ float g_M[B_];                      // per-batch global max
__device__ float g_invT[B_];                   // per-batch 1/sumexp
__device__ int   g_mask_is_byte;               // mask dtype flag (detected)

// ---------------------------------------------------------------------------
// Kernel 0: detect mask element width. Scan first 8192 uint32 words (safe
// under both layouts). Byte-bool layout has a word >1 with prob 1-(1/8)^8192.
// ---------------------------------------------------------------------------
__global__ void k0_detect_mask(const unsigned int* __restrict__ mw)
{
    __shared__ int found[256];
    const int tid = threadIdx.x;
    int f = 0;
    for (int i = tid; i < 8192; i += 256)
        if (mw[i] > 1u) { f = 1; break; }
    found[tid] = f;
    __syncthreads();
    for (int off = 128; off; off >>= 1) {
        if (tid < off) found[tid] |= found[tid + off];
        __syncthreads();
    }
    if (tid == 0) g_mask_is_byte = found[0];
}

// ---------------------------------------------------------------------------
// Kernel 1: one block per (batch, 256-row S-tile). Each warp owns 32
// contiguous rows; active rows found once via ballot, then walked as set
// bits with 2-row software pipelining (8 LDG.128 in flight). Online softmax
// with LAZY accumulator rescale (only when max increases; warp-uniform).
// Raw scores staged in smem, stored coalesced. Masked rows never touch HBM.
// ---------------------------------------------------------------------------
__global__ __launch_bounds__(256)
void k1_scores_partials(const float* __restrict__ hid,
                        const float* __restrict__ enc,
                        const void* __restrict__ mask,
                        float* __restrict__ scores_out /* = d_out + B*H */)
{
    const int b = blockIdx.x / NTILES;
    const int t = blockIdx.x % NTILES;
    const int tid  = threadIdx.x;
    const int warp = tid >> 5;
    const int lane = tid & 31;

    __shared__ float4 sh_hid[H_ / 4];     // 2 KB
    __shared__ float  sm_scores[8][32];   // 1 KB
    __shared__ float  sm_ctx[8][H_];      // 16 KB
    __shared__ float  sm_m[8], sm_l[8];

    // decoder_hidden[b,:] -> smem
    {
        const float4* h4 = (const float4*)(hid + (size_t)b * H_);
        if (tid < H_ / 4) sh_hid[tid] = h4[tid];
    }
    sm_scores[warp][lane] = -INFINITY;
    __syncthreads();

    float4 hv[4];
#pragma unroll
    for (int j = 0; j < 4; ++j) hv[j] = sh_hid[lane + 32 * j];

    // this warp's 32 contiguous rows; one coalesced mask read + ballot
    const int row0 = t * STILE + warp * 32;
    bool keep;
    if (g_mask_is_byte)
        keep = ((const unsigned char*)mask)[(size_t)b * S_ + row0 + lane] != 0;
    else
        keep = ((const int*)mask)[(size_t)b * S_ + row0 + lane] != 0;
    unsigned bits = __ballot_sync(0xffffffffu, keep);

    const float4* base = (const float4*)enc + ((size_t)b * S_ + row0) * (H_ / 4);

    float acc[16];
#pragma unroll
    for (int k = 0; k < 16; ++k) acc[k] = 0.f;
    float m = -INFINITY, l = 0.f;

    while (bits) {
        const int r0 = __ffs(bits) - 1; bits &= bits - 1;
        int r1 = -1;
        if (bits) { r1 = __ffs(bits) - 1; bits &= bits - 1; }

        // issue ALL loads for both rows before any math (MLP=8)
        float4 v0[4], v1[4];
#pragma unroll
        for (int j = 0; j < 4; ++j) v0[j] = base[(size_t)r0 * (H_/4) + lane + 32 * j];
        if (r1 >= 0) {
#pragma unroll
            for (int j = 0; j < 4; ++j) v1[j] = base[(size_t)r1 * (H_/4) + lane + 32 * j];
        }

        float p0 = 0.f, p1 = 0.f;
#pragma unroll
        for (int j = 0; j < 4; ++j)
            p0 += v0[j].x*hv[j].x + v0[j].y*hv[j].y + v0[j].z*hv[j].z + v0[j].w*hv[j].w;
        if (r1 >= 0) {
#pragma unroll
            for (int j = 0; j < 4; ++j)
                p1 += v1[j].x*hv[j].x + v1[j].y*hv[j].y + v1[j].z*hv[j].z + v1[j].w*hv[j].w;
        }
        // two independent reductions, pipelined
#pragma unroll
        for (int off = 16; off; off >>= 1) {
            p0 += __shfl_xor_sync(0xffffffffu, p0, off);
            p1 += __shfl_xor_sync(0xffffffffu, p1, off);
        }

        // row 0: lazy-rescale online softmax (branch is warp-uniform)
        if (p0 > m) {
            const float sc = __expf(m - p0);   // exp(-inf - x) = 0 first time
            l *= sc;
#pragma unroll
            for (int k = 0; k < 16; ++k) acc[k] *= sc;
            m = p0;
        }
        {
            const float e = __expf(p0 - m);
            l += e;
#pragma unroll
            for (int j = 0; j < 4; ++j) {
                acc[4*j+0] += e * v0[j].x; acc[4*j+1] += e * v0[j].y;
                acc[4*j+2] += e * v0[j].z; acc[4*j+3] += e * v0[j].w;
            }
            if (lane == 0) sm_scores[warp][r0] = p0;
        }
        // row 1
        if (r1 >= 0) {
            if (p1 > m) {
                const float sc = __expf(m - p1);
                l *= sc;
#pragma unroll
                for (int k = 0; k < 16; ++k) acc[k] *= sc;
                m = p1;
            }
            const float e = __expf(p1 - m);
            l += e;
#pragma unroll
            for (int j = 0; j < 4; ++j) {
                acc[4*j+0] += e * v1[j].x; acc[4*j+1] += e * v1[j].y;
                acc[4*j+2] += e * v1[j].z; acc[4*j+3] += e * v1[j].w;
            }
            if (lane == 0) sm_scores[warp][r1] = p1;
        }
    }

    __syncwarp();
    // one coalesced 128B score store per warp
    scores_out[(size_t)b * S_ + row0 + lane] = sm_scores[warp][lane];

    if (lane == 0) { sm_m[warp] = m; sm_l[warp] = l; }
    __syncthreads();

    // block max over the 8 warps
    float Mblk = -INFINITY;
#pragma unroll
    for (int w = 0; w < 8; ++w) Mblk = fmaxf(Mblk, sm_m[w]);

    // scale this warp's accumulator to the block max, dump to smem (float4)
    const float wscale = (m > -INFINITY) ? __expf(m - Mblk) : 0.f;
    float4* dst = (float4*)sm_ctx[warp];
#pragma unroll
    for (int j = 0; j < 4; ++j)
        dst[lane + 32 * j] = make_float4(acc[4*j+0] * wscale, acc[4*j+1] * wscale,
                                         acc[4*j+2] * wscale, acc[4*j+3] * wscale);
    __syncthreads();

    // reduce 8 warps -> per-tile partial context
    float* part = g_partial + (size_t)(b * NTILES + t) * H_;
    for (int h = tid; h < H_; h += 256) {
        float c = 0.f;
#pragma unroll
        for (int w = 0; w < 8; ++w) c += sm_ctx[w][h];
        part[h] = c;
    }

    if (tid == 0) {
        float L = 0.f;
#pragma unroll
        for (int w = 0; w < 8; ++w) {
            const float sc = (sm_m[w] > -INFINITY) ? __expf(sm_m[w] - Mblk) : 0.f;
            L += sm_l[w] * sc;
        }
        g_m[b * NTILES + t] = Mblk;
        g_l[b * NTILES + t] = L;
    }
}

// ---------------------------------------------------------------------------
// Kernel 2: one block per batch. Combine 32 tile partials -> context, and
// produce per-batch (M, 1/T) for the weights pass.
// ---------------------------------------------------------------------------
__global__ __launch_bounds__(256)
void k2_combine(float* __restrict__ ctx_out /* = d_out */)
{
    const int b   = blockIdx.x;
    const int tid = threadIdx.x;

    __shared__ float sc[NTILES];
    __shared__ float sh_M, sh_invT;

    if (tid == 0) {
        float Mb = -INFINITY;
        for (int t = 0; t < NTILES; ++t) Mb = fmaxf(Mb, g_m[b * NTILES + t]);
        sh_M = Mb;
    }
    __syncthreads();
    const float Mb = sh_M;

    if (tid < NTILES) {
        const float mt = g_m[b * NTILES + tid];
        sc[tid] = (mt > -INFINITY) ? __expf(mt - Mb) : 0.f;
    }
    __syncthreads();

    if (tid == 0) {
        float T = 0.f;
        for (int t = 0; t < NTILES; ++t) T += g_l[b * NTILES + t] * sc[t];
        const float invT = 1.f / T;
        sh_invT = invT;
        g_M[b] = Mb;
        g_invT[b] = invT;
    }
    __syncthreads();
    const float invT = sh_invT;

    for (int h = tid; h < H_; h += 256) {
        float c = 0.f;
#pragma unroll
        for (int t = 0; t < NTILES; ++t)
            c += g_partial[(size_t)(b * NTILES + t) * H_ + h] * sc[t];
        ctx_out[(size_t)b * H_ + h] = c * invT;
    }
}

// ---------------------------------------------------------------------------
// Kernel 3: finalize weights in place (float4): w = exp(score - M_b) * invT_b
// ---------------------------------------------------------------------------
__global__ __launch_bounds__(256)
void k3_weights(float4* __restrict__ scores4 /* = d_out + B*H, as float4 */)
{
    const int idx = blockIdx.x * 256 + threadIdx.x;   // float4 index
    if (idx >= B_ * S_ / 4) return;
    const int b = idx / (S_ / 4);
    const float M = g_M[b];
    const float iT = g_invT[b];
    float4 s = scores4[idx];
    s.x = __expf(s.x - M) * iT;
    s.y = __expf(s.y - M) * iT;
    s.z = __expf(s.z - M) * iT;
    s.w = __expf(s.w - M) * iT;
    scores4[idx] = s;
}

// ---------------------------------------------------------------------------
extern "C" void kernel_launch(void* const* d_in, const int* in_sizes, int n_in,
                              void* d_out, int out_size)
{
    const float* hid  = (const float*)d_in[0];   // [B,H]
    const float* enc  = (const float*)d_in[1];   // [B,S,H]
    const void*  mask = d_in[2];                 // [B,S] bool (width detected)

    float* ctx     = (float*)d_out;            // [B,H]
    float* weights = (float*)d_out + B_ * H_;  // [B,S]

    k0_detect_mask<<<1, 256>>>((const unsigned int*)mask);
    k1_scores_partials<<<NBLOCKS1, 256>>>(hid, enc, mask, weights);
    k2_combine<<<B_, 256>>>(ctx);
    k3_weights<<<(B_ * S_ / 4 + 255) / 256, 256>>>((float4*)weights);
}

// round 4
// speedup vs baseline: 3.1296x; 1.1973x over previous
#include <cuda_runtime.h>
#include <math.h>

// Problem constants (fixed by the reference)
#define B_  64
#define S_  8192
#define H_  512
#define STILE 256
#define NTILES (S_ / STILE)    // 32
#define NBLOCKS1 (B_ * NTILES) // 2048

// Scratch (allocation-free: __device__ globals)
__device__ float g_partial[B_ * NTILES * H_];  // 4 MB: per-tile partial context
__device__ float g_m[B_ * NTILES];             // per-tile local max
__device__ float g_l[B_ * NTILES];             // per-tile local sumexp
__device__ float g_M[B_];                      // per-batch global max
__device__ float g_invT[B_];                   // per-batch 1/sumexp
__device__ int   g_mask_is_byte;               // mask dtype flag (detected)

// ---------------------------------------------------------------------------
// Kernel 0: detect mask element width. Branch-free OR-scan of the first 2048
// uint32 words (safe under both layouts). If byte-bools, P(all words <=1)
// = (1/8)^2048 ~ 0. Single block, 8 independent loads per thread.
// ---------------------------------------------------------------------------
__global__ void k0_detect_mask(const unsigned int* __restrict__ mw)
{
    __shared__ int found[256];
    const int tid = threadIdx.x;
    unsigned int v = 0;
#pragma unroll
    for (int j = 0; j < 8; ++j) v |= mw[tid + 256 * j];
    found[tid] = (v > 1u) ? 1 : 0;
    __syncthreads();
    for (int off = 128; off; off >>= 1) {
        if (tid < off) found[tid] |= found[tid + off];
        __syncthreads();
    }
    if (tid == 0) g_mask_is_byte = found[0];
}

// ---------------------------------------------------------------------------
// Kernel 1: one block per (batch, 256-row S-tile). Each warp owns 32
// contiguous rows; active rows found once via ballot, then walked 4 at a
// time: all 16 LDG.128 issued before any math (MLP=16), 4 dots with split
// partial sums (short FMA chains), 4-way interleaved shfl reduction, ONE
// lazy rescale per 4-row group. Masked rows never touch HBM.
// ---------------------------------------------------------------------------
__global__ __launch_bounds__(256)
void k1_scores_partials(const float* __restrict__ hid,
                        const float* __restrict__ enc,
                        const void* __restrict__ mask,
                        float* __restrict__ scores_out /* = d_out + B*H */)
{
    const int b = blockIdx.x / NTILES;
    const int t = blockIdx.x % NTILES;
    const int tid  = threadIdx.x;
    const int warp = tid >> 5;
    const int lane = tid & 31;

    __shared__ float4 sh_hid[H_ / 4];     // 2 KB
    __shared__ float  sm_scores[8][32];   // 1 KB
    __shared__ float  sm_ctx[8][H_];      // 16 KB
    __shared__ float  sm_m[8], sm_l[8];

    // decoder_hidden[b,:] -> smem
    {
        const float4* h4 = (const float4*)(hid + (size_t)b * H_);
        if (tid < H_ / 4) sh_hid[tid] = h4[tid];
    }
    sm_scores[warp][lane] = -INFINITY;
    __syncthreads();

    float4 hv[4];
#pragma unroll
    for (int j = 0; j < 4; ++j) hv[j] = sh_hid[lane + 32 * j];

    // this warp's 32 contiguous rows; one coalesced mask read + ballot
    const int row0 = t * STILE + warp * 32;
    bool keep;
    if (g_mask_is_byte)
        keep = ((const unsigned char*)mask)[(size_t)b * S_ + row0 + lane] != 0;
    else
        keep = ((const int*)mask)[(size_t)b * S_ + row0 + lane] != 0;
    unsigned bits = __ballot_sync(0xffffffffu, keep);

    const float4* base = (const float4*)enc + ((size_t)b * S_ + row0) * (H_ / 4);

    float acc[16];
#pragma unroll
    for (int k = 0; k < 16; ++k) acc[k] = 0.f;
    float m = -INFINITY, l = 0.f;

    while (bits) {
        // pull up to 4 set bits
        int r[4];
        int n = 0;
#pragma unroll
        for (int q = 0; q < 4; ++q) {
            if (bits) { r[q] = __ffs(bits) - 1; bits &= bits - 1; ++n; }
            else        r[q] = r[0];   // duplicate row 0 (weight forced to 0)
        }

        // issue ALL loads before any math (up to 16 LDG.128 in flight)
        float4 v[4][4];
#pragma unroll
        for (int q = 0; q < 4; ++q)
#pragma unroll
            for (int j = 0; j < 4; ++j)
                v[q][j] = base[(size_t)r[q] * (H_/4) + lane + 32 * j];

        // 4 dots, each via 4 independent partial sums (short chains)
        float p[4];
#pragma unroll
        for (int q = 0; q < 4; ++q) {
            float s0 = v[q][0].x*hv[0].x + v[q][0].y*hv[0].y + v[q][0].z*hv[0].z + v[q][0].w*hv[0].w;
            float s1 = v[q][1].x*hv[1].x + v[q][1].y*hv[1].y + v[q][1].z*hv[1].z + v[q][1].w*hv[1].w;
            float s2 = v[q][2].x*hv[2].x + v[q][2].y*hv[2].y + v[q][2].z*hv[2].z + v[q][2].w*hv[2].w;
            float s3 = v[q][3].x*hv[3].x + v[q][3].y*hv[3].y + v[q][3].z*hv[3].z + v[q][3].w*hv[3].w;
            p[q] = (s0 + s1) + (s2 + s3);
        }
        // 4 interleaved warp reductions (one 130-cyc chain for all 4 rows)
#pragma unroll
        for (int off = 16; off; off >>= 1) {
#pragma unroll
            for (int q = 0; q < 4; ++q)
                p[q] += __shfl_xor_sync(0xffffffffu, p[q], off);
        }

        // group max + single lazy rescale (warp-uniform branch)
        float gmax = p[0];
#pragma unroll
        for (int q = 1; q < 4; ++q) if (q < n) gmax = fmaxf(gmax, p[q]);
        if (gmax > m) {
            const float sc = __expf(m - gmax);   // exp(-inf - x) = 0 first time
            l *= sc;
#pragma unroll
            for (int k = 0; k < 16; ++k) acc[k] *= sc;
            m = gmax;
        }

        // accumulate all rows in the group
#pragma unroll
        for (int q = 0; q < 4; ++q) {
            float e = (q < n) ? __expf(p[q] - m) : 0.f;
            l += e;
#pragma unroll
            for (int j = 0; j < 4; ++j) {
                acc[4*j+0] += e * v[q][j].x; acc[4*j+1] += e * v[q][j].y;
                acc[4*j+2] += e * v[q][j].z; acc[4*j+3] += e * v[q][j].w;
            }
            if (lane == 0 && q < n) sm_scores[warp][r[q]] = p[q];
        }
    }

    __syncwarp();
    // one coalesced 128B score store per warp
    scores_out[(size_t)b * S_ + row0 + lane] = sm_scores[warp][lane];

    if (lane == 0) { sm_m[warp] = m; sm_l[warp] = l; }
    __syncthreads();

    // block max over the 8 warps
    float Mblk = -INFINITY;
#pragma unroll
    for (int w = 0; w < 8; ++w) Mblk = fmaxf(Mblk, sm_m[w]);

    // scale this warp's accumulator to the block max, dump to smem (float4)
    const float wscale = (m > -INFINITY) ? __expf(m - Mblk) : 0.f;
    float4* dst = (float4*)sm_ctx[warp];
#pragma unroll
    for (int j = 0; j < 4; ++j)
        dst[lane + 32 * j] = make_float4(acc[4*j+0] * wscale, acc[4*j+1] * wscale,
                                         acc[4*j+2] * wscale, acc[4*j+3] * wscale);
    __syncthreads();

    // reduce 8 warps -> per-tile partial context
    float* part = g_partial + (size_t)(b * NTILES + t) * H_;
    for (int h = tid; h < H_; h += 256) {
        float c = 0.f;
#pragma unroll
        for (int w = 0; w < 8; ++w) c += sm_ctx[w][h];
        part[h] = c;
    }

    if (tid == 0) {
        float L = 0.f;
#pragma unroll
        for (int w = 0; w < 8; ++w) {
            const float sc = (sm_m[w] > -INFINITY) ? __expf(sm_m[w] - Mblk) : 0.f;
            L += sm_l[w] * sc;
        }
        g_m[b * NTILES + t] = Mblk;
        g_l[b * NTILES + t] = L;
    }
}

// ---------------------------------------------------------------------------
// Kernel 2: one block per batch. Combine 32 tile partials -> context, and
// produce per-batch (M, 1/T) for the weights pass.
// ---------------------------------------------------------------------------
__global__ __launch_bounds__(256)
void k2_combine(float* __restrict__ ctx_out /* = d_out */)
{
    const int b   = blockIdx.x;
    const int tid = threadIdx.x;

    __shared__ float sc[NTILES];
    __shared__ float sh_M, sh_invT;

    if (tid == 0) {
        float Mb = -INFINITY;
        for (int t = 0; t < NTILES; ++t) Mb = fmaxf(Mb, g_m[b * NTILES + t]);
        sh_M = Mb;
    }
    __syncthreads();
    const float Mb = sh_M;

    if (tid < NTILES) {
        const float mt = g_m[b * NTILES + tid];
        sc[tid] = (mt > -INFINITY) ? __expf(mt - Mb) : 0.f;
    }
    __syncthreads();

    if (tid == 0) {
        float T = 0.f;
        for (int t = 0; t < NTILES; ++t) T += g_l[b * NTILES + t] * sc[t];
        const float invT = 1.f / T;
        sh_invT = invT;
        g_M[b] = Mb;
        g_invT[b] = invT;
    }
    __syncthreads();
    const float invT = sh_invT;

    for (int h = tid; h < H_; h += 256) {
        float c = 0.f;
#pragma unroll
        for (int t = 0; t < NTILES; ++t)
            c += g_partial[(size_t)(b * NTILES + t) * H_ + h] * sc[t];
        ctx_out[(size_t)b * H_ + h] = c * invT;
    }
}

// ---------------------------------------------------------------------------
// Kernel 3: finalize weights in place (float4): w = exp(score - M_b) * invT_b
// ---------------------------------------------------------------------------
__global__ __launch_bounds__(256)
void k3_weights(float4* __restrict__ scores4 /* = d_out + B*H, as float4 */)
{
    const int idx = blockIdx.x * 256 + threadIdx.x;   // float4 index
    if (idx >= B_ * S_ / 4) return;
    const int b = idx / (S_ / 4);
    const float M = g_M[b];
    const float iT = g_invT[b];
    float4 s = scores4[idx];
    s.x = __expf(s.x - M) * iT;
    s.y = __expf(s.y - M) * iT;
    s.z = __expf(s.z - M) * iT;
    s.w = __expf(s.w - M) * iT;
    scores4[idx] = s;
}

// ---------------------------------------------------------------------------
extern "C" void kernel_launch(void* const* d_in, const int* in_sizes, int n_in,
                              void* d_out, int out_size)
{
    const float* hid  = (const float*)d_in[0];   // [B,H]
    const float* enc  = (const float*)d_in[1];   // [B,S,H]
    const void*  mask = d_in[2];                 // [B,S] bool (width detected)

    float* ctx     = (float*)d_out;            // [B,H]
    float* weights = (float*)d_out + B_ * H_;  // [B,S]

    k0_detect_mask<<<1, 256>>>((const unsigned int*)mask);
    k1_scores_partials<<<NBLOCKS1, 256>>>(hid, enc, mask, weights);
    k2_combine<<<B_, 256>>>(ctx);
    k3_weights<<<(B_ * S_ / 4 + 255) / 256, 256>>>((float4*)weights);
}

// round 5
// speedup vs baseline: 3.2451x; 1.0369x over previous
#include <cuda_runtime.h>
#include <math.h>

// Problem constants (fixed by the reference)
#define B_  64
#define S_  8192
#define H_  512
#define STILE 512
#define NTILES (S_ / STILE)    // 16
#define NBLOCKS1 (B_ * NTILES) // 1024

// Scratch (allocation-free: __device__ globals)
__device__ float g_partial[B_ * NTILES * H_];  // 2 MB: per-tile partial context
__device__ float g_m[B_ * NTILES];             // per-tile local max
__device__ float g_l[B_ * NTILES];             // per-tile local sumexp

// ---------------------------------------------------------------------------
// In-kernel mask width detection: branch-free OR over the first 512 uint32
// words (2 KB, safe under both layouts; L2-resident after first block).
// Byte-bool layout yields a word > 1 with prob 1-(1/8)^512 ~ 1. Every block
// computes the same deterministic answer.
// ---------------------------------------------------------------------------
__device__ __forceinline__ int detect_mask_is_byte(const unsigned int* mw,
                                                   int tid, int* sh_flag)
{
    unsigned int v = mw[tid] | mw[tid + 256];   // 512 words over 256 threads
    unsigned any = __any_sync(0xffffffffu, v > 1u);
    if ((tid & 31) == 0) sh_flag[tid >> 5] = any ? 1 : 0;
    __syncthreads();
    int f = sh_flag[0] | sh_flag[1] | sh_flag[2] | sh_flag[3]
          | sh_flag[4] | sh_flag[5] | sh_flag[6] | sh_flag[7];
    return f;
}

// ---------------------------------------------------------------------------
// Kernel 1: one block per (batch, 512-row S-tile). Each warp owns 64
// contiguous rows; active rows found via two ballots (uint64), walked 4 at a
// time: 16 LDG.128 issued before any math (MLP=16), 4 dots with split
// partial sums, 4-way interleaved shfl reduction, ONE lazy rescale per
// group. Masked rows never touch HBM.
// ---------------------------------------------------------------------------
__global__ __launch_bounds__(256)
void k1_scores_partials(const float* __restrict__ hid,
                        const float* __restrict__ enc,
                        const void* __restrict__ mask,
                        float* __restrict__ scores_out /* = d_out + B*H */)
{
    const int b = blockIdx.x / NTILES;
    const int t = blockIdx.x % NTILES;
    const int tid  = threadIdx.x;
    const int warp = tid >> 5;
    const int lane = tid & 31;

    __shared__ float4 sh_hid[H_ / 4];     // 2 KB
    __shared__ float  sm_scores[8][64];   // 2 KB
    __shared__ float  sm_ctx[8][H_];      // 16 KB
    __shared__ float  sm_m[8], sm_l[8];
    __shared__ int    sh_flag[8];

    // decoder_hidden[b,:] -> smem (overlaps with detection loads)
    {
        const float4* h4 = (const float4*)(hid + (size_t)b * H_);
        if (tid < H_ / 4) sh_hid[tid] = h4[tid];
    }
    sm_scores[warp][lane]      = -INFINITY;
    sm_scores[warp][lane + 32] = -INFINITY;

    const int mask_is_byte =
        detect_mask_is_byte((const unsigned int*)mask, tid, sh_flag);
    __syncthreads();

    float4 hv[4];
#pragma unroll
    for (int j = 0; j < 4; ++j) hv[j] = sh_hid[lane + 32 * j];

    // this warp's 64 contiguous rows; two coalesced mask reads + ballots
    const int row0 = t * STILE + warp * 64;
    bool k0b, k1b;
    if (mask_is_byte) {
        const unsigned char* mp = (const unsigned char*)mask + (size_t)b * S_ + row0;
        k0b = mp[lane] != 0;  k1b = mp[lane + 32] != 0;
    } else {
        const int* mp = (const int*)mask + (size_t)b * S_ + row0;
        k0b = mp[lane] != 0;  k1b = mp[lane + 32] != 0;
    }
    unsigned long long bits =
        (unsigned long long)__ballot_sync(0xffffffffu, k0b)
      | ((unsigned long long)__ballot_sync(0xffffffffu, k1b) << 32);

    const float4* base = (const float4*)enc + ((size_t)b * S_ + row0) * (H_ / 4);

    float acc[16];
#pragma unroll
    for (int k = 0; k < 16; ++k) acc[k] = 0.f;
    float m = -INFINITY, l = 0.f;

    while (bits) {
        // pull up to 4 set bits
        int r[4];
        int n = 0;
#pragma unroll
        for (int q = 0; q < 4; ++q) {
            if (bits) { r[q] = __ffsll(bits) - 1; bits &= bits - 1; ++n; }
            else        r[q] = r[0];   // duplicate row 0 (weight forced to 0)
        }

        // issue ALL loads before any math (up to 16 LDG.128 in flight)
        float4 v[4][4];
#pragma unroll
        for (int q = 0; q < 4; ++q)
#pragma unroll
            for (int j = 0; j < 4; ++j)
                v[q][j] = base[(size_t)r[q] * (H_/4) + lane + 32 * j];

        // 4 dots, each via 4 independent partial sums (short chains)
        float p[4];
#pragma unroll
        for (int q = 0; q < 4; ++q) {
            float s0 = v[q][0].x*hv[0].x + v[q][0].y*hv[0].y + v[q][0].z*hv[0].z + v[q][0].w*hv[0].w;
            float s1 = v[q][1].x*hv[1].x + v[q][1].y*hv[1].y + v[q][1].z*hv[1].z + v[q][1].w*hv[1].w;
            float s2 = v[q][2].x*hv[2].x + v[q][2].y*hv[2].y + v[q][2].z*hv[2].z + v[q][2].w*hv[2].w;
            float s3 = v[q][3].x*hv[3].x + v[q][3].y*hv[3].y + v[q][3].z*hv[3].z + v[q][3].w*hv[3].w;
            p[q] = (s0 + s1) + (s2 + s3);
        }
        // 4 interleaved warp reductions (one latency chain for all 4 rows)
#pragma unroll
        for (int off = 16; off; off >>= 1) {
#pragma unroll
            for (int q = 0; q < 4; ++q)
                p[q] += __shfl_xor_sync(0xffffffffu, p[q], off);
        }

        // group max + single lazy rescale (warp-uniform branch)
        float gmax = p[0];
#pragma unroll
        for (int q = 1; q < 4; ++q) if (q < n) gmax = fmaxf(gmax, p[q]);
        if (gmax > m) {
            const float sc = __expf(m - gmax);   // exp(-inf - x) = 0 first time
            l *= sc;
#pragma unroll
            for (int k = 0; k < 16; ++k) acc[k] *= sc;
            m = gmax;
        }

        // accumulate all rows in the group
#pragma unroll
        for (int q = 0; q < 4; ++q) {
            float e = (q < n) ? __expf(p[q] - m) : 0.f;
            l += e;
#pragma unroll
            for (int j = 0; j < 4; ++j) {
                acc[4*j+0] += e * v[q][j].x; acc[4*j+1] += e * v[q][j].y;
                acc[4*j+2] += e * v[q][j].z; acc[4*j+3] += e * v[q][j].w;
            }
            if (lane == 0 && q < n) sm_scores[warp][r[q]] = p[q];
        }
    }

    __syncwarp();
    // two coalesced 128B score stores per warp
    scores_out[(size_t)b * S_ + row0 + lane]      = sm_scores[warp][lane];
    scores_out[(size_t)b * S_ + row0 + lane + 32] = sm_scores[warp][lane + 32];

    if (lane == 0) { sm_m[warp] = m; sm_l[warp] = l; }
    __syncthreads();

    // block max over the 8 warps
    float Mblk = -INFINITY;
#pragma unroll
    for (int w = 0; w < 8; ++w) Mblk = fmaxf(Mblk, sm_m[w]);

    // scale this warp's accumulator to the block max, dump to smem (float4)
    const float wscale = (m > -INFINITY) ? __expf(m - Mblk) : 0.f;
    float4* dst = (float4*)sm_ctx[warp];
#pragma unroll
    for (int j = 0; j < 4; ++j)
        dst[lane + 32 * j] = make_float4(acc[4*j+0] * wscale, acc[4*j+1] * wscale,
                                         acc[4*j+2] * wscale, acc[4*j+3] * wscale);
    __syncthreads();

    // reduce 8 warps -> per-tile partial context
    float* part = g_partial + (size_t)(b * NTILES + t) * H_;
    for (int h = tid; h < H_; h += 256) {
        float c = 0.f;
#pragma unroll
        for (int w = 0; w < 8; ++w) c += sm_ctx[w][h];
        part[h] = c;
    }

    if (tid == 0) {
        float L = 0.f;
#pragma unroll
        for (int w = 0; w < 8; ++w) {
            const float sc = (sm_m[w] > -INFINITY) ? __expf(sm_m[w] - Mblk) : 0.f;
            L += sm_l[w] * sc;
        }
        g_m[b * NTILES + t] = Mblk;
        g_l[b * NTILES + t] = L;
    }
}

// ---------------------------------------------------------------------------
// Per-batch (M, invT) from the tiny g_m/g_l arrays — warp 0, shfl reduce.
// Called by both k2 and k3 (independent, so they can run concurrently).
// ---------------------------------------------------------------------------
__device__ __forceinline__ void batch_stats(int b, int tid,
                                            float* sh_M, float* sh_invT)
{
    if (tid < 32) {
        float mt = (tid < NTILES) ? g_m[b * NTILES + tid] : -INFINITY;
        float lt = (tid < NTILES) ? g_l[b * NTILES + tid] : 0.f;
        float Mb = mt;
#pragma unroll
        for (int off = 16; off; off >>= 1)
            Mb = fmaxf(Mb, __shfl_xor_sync(0xffffffffu, Mb, off));
        float c = (mt > -INFINITY) ? lt * __expf(mt - Mb) : 0.f;
#pragma unroll
        for (int off = 16; off; off >>= 1)
            c += __shfl_xor_sync(0xffffffffu, c, off);
        if (tid == 0) { *sh_M = Mb; *sh_invT = 1.f / c; }
    }
    __syncthreads();
}

// ---------------------------------------------------------------------------
// Kernel 2: one block per batch. Combine 16 tile partials -> context.
// Depends only on k1.
// ---------------------------------------------------------------------------
__global__ __launch_bounds__(256)
void k2_combine(float* __restrict__ ctx_out /* = d_out */)
{
    const int b   = blockIdx.x;
    const int tid = threadIdx.x;

    __shared__ float sh_M, sh_invT;
    __shared__ float sc[NTILES];

    batch_stats(b, tid, &sh_M, &sh_invT);
    if (tid < NTILES) {
        const float mt = g_m[b * NTILES + tid];
        sc[tid] = (mt > -INFINITY) ? __expf(mt - sh_M) : 0.f;
    }
    __syncthreads();
    const float invT = sh_invT;

    for (int h = tid; h < H_; h += 256) {
        float c = 0.f;
#pragma unroll
        for (int t = 0; t < NTILES; ++t)
            c += g_partial[(size_t)(b * NTILES + t) * H_ + h] * sc[t];
        ctx_out[(size_t)b * H_ + h] = c * invT;
    }
}

// ---------------------------------------------------------------------------
// Kernel 3: one block per batch. Recomputes (M, invT) from g_m/g_l, then
// finalizes weights in place (float4). Depends only on k1 -> runs
// concurrently with k2.
// ---------------------------------------------------------------------------
__global__ __launch_bounds__(256)
void k3_weights(float4* __restrict__ scores4 /* = d_out + B*H, as float4 */)
{
    const int b   = blockIdx.x;
    const int tid = threadIdx.x;

    __shared__ float sh_M, sh_invT;
    batch_stats(b, tid, &sh_M, &sh_invT);
    const float M  = sh_M;
    const float iT = sh_invT;

    float4* p = scores4 + (size_t)b * (S_ / 4);
#pragma unroll
    for (int i = 0; i < (S_ / 4) / 256; ++i) {   // 8 iterations
        float4 s = p[tid + 256 * i];
        s.x = __expf(s.x - M) * iT;
        s.y = __expf(s.y - M) * iT;
        s.z = __expf(s.z - M) * iT;
        s.w = __expf(s.w - M) * iT;
        p[tid + 256 * i] = s;
    }
}

// ---------------------------------------------------------------------------
extern "C" void kernel_launch(void* const* d_in, const int* in_sizes, int n_in,
                              void* d_out, int out_size)
{
    const float* hid  = (const float*)d_in[0];   // [B,H]
    const float* enc  = (const float*)d_in[1];   // [B,S,H]
    const void*  mask = d_in[2];                 // [B,S] bool (width detected)

    float* ctx     = (float*)d_out;            // [B,H]
    float* weights = (float*)d_out + B_ * H_;  // [B,S]

    k1_scores_partials<<<NBLOCKS1, 256>>>(hid, enc, mask, weights);
    k2_combine<<<B_, 256>>>(ctx);
    k3_weights<<<B_, 256>>>((float4*)weights);
}

// round 6
// speedup vs baseline: 3.4532x; 1.0642x over previous
#include <cuda_runtime.h>
#include <math.h>

// Problem constants (fixed by the reference)
#define B_  64
#define S_  8192
#define H_  512
#define STILE 512
#define NTILES (S_ / STILE)    // 16
#define NBLOCKS1 (B_ * NTILES) // 1024

// Scratch (allocation-free: __device__ globals)
__device__ float g_partial[B_ * NTILES * H_];  // 2 MB
__device__ float g_m[B_ * NTILES];
__device__ float g_l[B_ * NTILES];

// Dynamic smem layout (bytes)
#define OFF_HID     0                         // 2048  (128 float4)
#define OFF_CTX     2048                      // 16384 (8 x 512 floats)
#define OFF_SCORES  (2048 + 16384)            // 2048  (8 x 64 floats)
#define OFF_ROWS    (OFF_SCORES + 2048)       // 512   (8 x 64 bytes)
#define OFF_M       (OFF_ROWS + 512)          // 32
#define OFF_L       (OFF_M + 32)              // 32
#define OFF_FLAG    (OFF_L + 32)              // 32
#define OFF_STAGE   ((OFF_FLAG + 32 + 127) & ~127)   // 128-aligned
#define STAGE_PER_WARP 8192                   // 2 bufs x 2 rows x 2048 B
#define SMEM_TOTAL  (OFF_STAGE + 8 * STAGE_PER_WARP) // ~86.7 KB

// ---------------------------------------------------------------------------
// Kernel 1: one block per (batch, 512-row S-tile). Each warp owns 64 rows.
// Active rows compacted into a smem list (ballot+popc). Main loop walks the
// list 2 rows per group with a DOUBLE-BUFFERED cp.async pipeline: group g+1
// streams HBM->smem while group g is computed from smem. Load depth is thus
// independent of registers -> HBM latency fully covered.
// ---------------------------------------------------------------------------
__global__ __launch_bounds__(256)
void k1_scores_partials(const float* __restrict__ hid,
                        const float* __restrict__ enc,
                        const void* __restrict__ mask,
                        float* __restrict__ scores_out /* = d_out + B*H */)
{
    extern __shared__ char dsm[];
    float4*        sh_hid    = (float4*)(dsm + OFF_HID);
    float*         sm_ctx    = (float*)(dsm + OFF_CTX);
    float*         sm_scores = (float*)(dsm + OFF_SCORES);
    unsigned char* sm_rows   = (unsigned char*)(dsm + OFF_ROWS);
    float*         sm_m      = (float*)(dsm + OFF_M);
    float*         sm_l      = (float*)(dsm + OFF_L);
    int*           sh_flag   = (int*)(dsm + OFF_FLAG);

    const int b = blockIdx.x / NTILES;
    const int t = blockIdx.x % NTILES;
    const int tid  = threadIdx.x;
    const int warp = tid >> 5;
    const int lane = tid & 31;

    // decoder_hidden[b,:] -> smem
    {
        const float4* h4 = (const float4*)(hid + (size_t)b * H_);
        if (tid < H_ / 4) sh_hid[tid] = h4[tid];
    }
    sm_scores[warp * 64 + lane]      = -INFINITY;
    sm_scores[warp * 64 + lane + 32] = -INFINITY;

    // mask width detection: branch-free OR over first 512 words (safe under
    // both layouts; byte-bools give a word>1 with prob 1-(1/8)^512 ~ 1)
    {
        const unsigned int* mw = (const unsigned int*)mask;
        unsigned int v = mw[tid] | mw[tid + 256];
        unsigned any = __any_sync(0xffffffffu, v > 1u);
        if (lane == 0) sh_flag[warp] = any ? 1 : 0;
    }
    __syncthreads();
    const int mask_is_byte = sh_flag[0] | sh_flag[1] | sh_flag[2] | sh_flag[3]
                           | sh_flag[4] | sh_flag[5] | sh_flag[6] | sh_flag[7];

    float4 hv[4];
#pragma unroll
    for (int j = 0; j < 4; ++j) hv[j] = sh_hid[lane + 32 * j];

    // this warp's 64 rows: ballots + parallel compaction into sm_rows
    const int row0 = t * STILE + warp * 64;
    bool k0b, k1b;
    if (mask_is_byte) {
        const unsigned char* mp = (const unsigned char*)mask + (size_t)b * S_ + row0;
        k0b = mp[lane] != 0;  k1b = mp[lane + 32] != 0;
    } else {
        const int* mp = (const int*)mask + (size_t)b * S_ + row0;
        k0b = mp[lane] != 0;  k1b = mp[lane + 32] != 0;
    }
    const unsigned b0 = __ballot_sync(0xffffffffu, k0b);
    const unsigned b1 = __ballot_sync(0xffffffffu, k1b);
    const unsigned lmask = (lane == 31) ? 0x7fffffffu : ((1u << lane) - 1u);
    if (k0b) sm_rows[warp * 64 + __popc(b0 & lmask)] = (unsigned char)lane;
    if (k1b) sm_rows[warp * 64 + __popc(b0) + __popc(b1 & lmask)] = (unsigned char)(lane + 32);
    const int cnt = __popc(b0) + __popc(b1);
    __syncwarp();

    const char* gbase = (const char*)(enc + ((size_t)b * S_ + row0) * H_);
    char* stage = dsm + OFF_STAGE + warp * STAGE_PER_WARP;

    float acc[16];
#pragma unroll
    for (int k = 0; k < 16; ++k) acc[k] = 0.f;
    float m = -INFINITY, l = 0.f;

    const int ngroups = (cnt + 1) >> 1;

    if (ngroups > 0) {
        // prologue: stage group 0 into buf 0
        {
            const int r0 = sm_rows[warp * 64 + 0];
            const int r1 = (1 < cnt) ? sm_rows[warp * 64 + 1] : r0;
            unsigned int s0 = (unsigned int)__cvta_generic_to_shared(stage) + lane * 16;
            const char* g0 = gbase + (size_t)r0 * 2048 + lane * 16;
            const char* g1 = gbase + (size_t)r1 * 2048 + lane * 16;
#pragma unroll
            for (int j = 0; j < 4; ++j) {
                asm volatile("cp.async.cg.shared.global [%0], [%1], 16;"
                             :: "r"(s0 + j * 512), "l"(g0 + j * 512));
                asm volatile("cp.async.cg.shared.global [%0], [%1], 16;"
                             :: "r"(s0 + 2048 + j * 512), "l"(g1 + j * 512));
            }
            asm volatile("cp.async.commit_group;" ::: "memory");
        }

        for (int g = 0; g < ngroups; ++g) {
            __syncwarp();   // prior group's reads done before buffer reuse
            const bool has_next = (g + 1) < ngroups;
            if (has_next) {
                const int i0 = 2 * (g + 1);
                const int n0 = sm_rows[warp * 64 + i0];
                const int n1 = (i0 + 1 < cnt) ? sm_rows[warp * 64 + i0 + 1] : n0;
                char* buf = stage + ((g + 1) & 1) * 4096;
                unsigned int s0 = (unsigned int)__cvta_generic_to_shared(buf) + lane * 16;
                const char* g0 = gbase + (size_t)n0 * 2048 + lane * 16;
                const char* g1 = gbase + (size_t)n1 * 2048 + lane * 16;
#pragma unroll
                for (int j = 0; j < 4; ++j) {
                    asm volatile("cp.async.cg.shared.global [%0], [%1], 16;"
                                 :: "r"(s0 + j * 512), "l"(g0 + j * 512));
                    asm volatile("cp.async.cg.shared.global [%0], [%1], 16;"
                                 :: "r"(s0 + 2048 + j * 512), "l"(g1 + j * 512));
                }
                asm volatile("cp.async.commit_group;" ::: "memory");
                asm volatile("cp.async.wait_group 1;" ::: "memory");
            } else {
                asm volatile("cp.async.wait_group 0;" ::: "memory");
            }
            __syncwarp();   // make staged bytes visible across lanes

            const int i0 = 2 * g;
            const int r0 = sm_rows[warp * 64 + i0];
            const bool v1 = (i0 + 1) < cnt;
            const int r1 = v1 ? sm_rows[warp * 64 + i0 + 1] : r0;

            const float4* buf = (const float4*)(stage + (g & 1) * 4096);
            float4 v[2][4];
#pragma unroll
            for (int j = 0; j < 4; ++j) {
                v[0][j] = buf[lane + 32 * j];
                v[1][j] = buf[128 + lane + 32 * j];
            }

            float p0, p1;
            {
                float s0 = v[0][0].x*hv[0].x + v[0][0].y*hv[0].y + v[0][0].z*hv[0].z + v[0][0].w*hv[0].w;
                float s1 = v[0][1].x*hv[1].x + v[0][1].y*hv[1].y + v[0][1].z*hv[1].z + v[0][1].w*hv[1].w;
                float s2 = v[0][2].x*hv[2].x + v[0][2].y*hv[2].y + v[0][2].z*hv[2].z + v[0][2].w*hv[2].w;
                float s3 = v[0][3].x*hv[3].x + v[0][3].y*hv[3].y + v[0][3].z*hv[3].z + v[0][3].w*hv[3].w;
                p0 = (s0 + s1) + (s2 + s3);
            }
            {
                float s0 = v[1][0].x*hv[0].x + v[1][0].y*hv[0].y + v[1][0].z*hv[0].z + v[1][0].w*hv[0].w;
                float s1 = v[1][1].x*hv[1].x + v[1][1].y*hv[1].y + v[1][1].z*hv[1].z + v[1][1].w*hv[1].w;
                float s2 = v[1][2].x*hv[2].x + v[1][2].y*hv[2].y + v[1][2].z*hv[2].z + v[1][2].w*hv[2].w;
                float s3 = v[1][3].x*hv[3].x + v[1][3].y*hv[3].y + v[1][3].z*hv[3].z + v[1][3].w*hv[3].w;
                p1 = (s0 + s1) + (s2 + s3);
            }
#pragma unroll
            for (int off = 16; off; off >>= 1) {
                p0 += __shfl_xor_sync(0xffffffffu, p0, off);
                p1 += __shfl_xor_sync(0xffffffffu, p1, off);
            }

            const float gmax = v1 ? fmaxf(p0, p1) : p0;
            if (gmax > m) {
                const float sc = __expf(m - gmax);  // exp(-inf - x) = 0 first time
                l *= sc;
#pragma unroll
                for (int k = 0; k < 16; ++k) acc[k] *= sc;
                m = gmax;
            }
            const float e0 = __expf(p0 - m);
            const float e1 = v1 ? __expf(p1 - m) : 0.f;
            l += e0 + e1;
#pragma unroll
            for (int j = 0; j < 4; ++j) {
                acc[4*j+0] += e0 * v[0][j].x + e1 * v[1][j].x;
                acc[4*j+1] += e0 * v[0][j].y + e1 * v[1][j].y;
                acc[4*j+2] += e0 * v[0][j].z + e1 * v[1][j].z;
                acc[4*j+3] += e0 * v[0][j].w + e1 * v[1][j].w;
            }
            if (lane == 0) {
                sm_scores[warp * 64 + r0] = p0;
                if (v1) sm_scores[warp * 64 + r1] = p1;
            }
        }
    }

    __syncwarp();
    // coalesced score stores
    scores_out[(size_t)b * S_ + row0 + lane]      = sm_scores[warp * 64 + lane];
    scores_out[(size_t)b * S_ + row0 + lane + 32] = sm_scores[warp * 64 + lane + 32];

    if (lane == 0) { sm_m[warp] = m; sm_l[warp] = l; }
    __syncthreads();

    // block max over the 8 warps
    float Mblk = -INFINITY;
#pragma unroll
    for (int w = 0; w < 8; ++w) Mblk = fmaxf(Mblk, sm_m[w]);

    // scale this warp's accumulator to the block max, dump to smem (float4)
    const float wscale = (m > -INFINITY) ? __expf(m - Mblk) : 0.f;
    float4* dst = (float4*)(sm_ctx + warp * H_);
#pragma unroll
    for (int j = 0; j < 4; ++j)
        dst[lane + 32 * j] = make_float4(acc[4*j+0] * wscale, acc[4*j+1] * wscale,
                                         acc[4*j+2] * wscale, acc[4*j+3] * wscale);
    __syncthreads();

    // reduce 8 warps -> per-tile partial context
    float* part = g_partial + (size_t)(b * NTILES + t) * H_;
    for (int h = tid; h < H_; h += 256) {
        float c = 0.f;
#pragma unroll
        for (int w = 0; w < 8; ++w) c += sm_ctx[w * H_ + h];
        part[h] = c;
    }

    if (tid == 0) {
        float L = 0.f;
#pragma unroll
        for (int w = 0; w < 8; ++w) {
            const float sc = (sm_m[w] > -INFINITY) ? __expf(sm_m[w] - Mblk) : 0.f;
            L += sm_l[w] * sc;
        }
        g_m[b * NTILES + t] = Mblk;
        g_l[b * NTILES + t] = L;
    }
}

// ---------------------------------------------------------------------------
// Per-batch (M, invT) from the tiny g_m/g_l arrays — warp 0, shfl reduce.
// ---------------------------------------------------------------------------
__device__ __forceinline__ void batch_stats(int b, int tid,
                                            float* sh_M, float* sh_invT)
{
    if (tid < 32) {
        float mt = (tid < NTILES) ? g_m[b * NTILES + tid] : -INFINITY;
        float lt = (tid < NTILES) ? g_l[b * NTILES + tid] : 0.f;
        float Mb = mt;
#pragma unroll
        for (int off = 16; off; off >>= 1)
            Mb = fmaxf(Mb, __shfl_xor_sync(0xffffffffu, Mb, off));
        float c = (mt > -INFINITY) ? lt * __expf(mt - Mb) : 0.f;
#pragma unroll
        for (int off = 16; off; off >>= 1)
            c += __shfl_xor_sync(0xffffffffu, c, off);
        if (tid == 0) { *sh_M = Mb; *sh_invT = 1.f / c; }
    }
    __syncthreads();
}

// ---------------------------------------------------------------------------
// Kernel 2 (fused tail): grid (5, 64). slice 0 -> context combine;
// slices 1..4 -> weights quarters (in place on d_out scores).
// ---------------------------------------------------------------------------
__global__ __launch_bounds__(256)
void k2_fused(float* __restrict__ ctx_out /* d_out */,
              float4* __restrict__ scores4 /* d_out + B*H */)
{
    const int slice = blockIdx.x;   // 0..4
    const int b     = blockIdx.y;
    const int tid   = threadIdx.x;

    __shared__ float sh_M, sh_invT;
    batch_stats(b, tid, &sh_M, &sh_invT);
    const float M  = sh_M;
    const float iT = sh_invT;

    if (slice == 0) {
        __shared__ float sc[NTILES];
        if (tid < NTILES) {
            const float mt = g_m[b * NTILES + tid];
            sc[tid] = (mt > -INFINITY) ? __expf(mt - M) : 0.f;
        }
        __syncthreads();
        for (int h = tid; h < H_; h += 256) {
            float c = 0.f;
#pragma unroll
            for (int t = 0; t < NTILES; ++t)
                c += g_partial[(size_t)(b * NTILES + t) * H_ + h] * sc[t];
            ctx_out[(size_t)b * H_ + h] = c * iT;
        }
    } else {
        // weights quarter: 512 float4 per slice
        float4* p = scores4 + (size_t)b * (S_ / 4) + (slice - 1) * 512;
#pragma unroll
        for (int i = 0; i < 2; ++i) {
            float4 s = p[tid + 256 * i];
            s.x = __expf(s.x - M) * iT;
            s.y = __expf(s.y - M) * iT;
            s.z = __expf(s.z - M) * iT;
            s.w = __expf(s.w - M) * iT;
            p[tid + 256 * i] = s;
        }
    }
}

// ---------------------------------------------------------------------------
extern "C" void kernel_launch(void* const* d_in, const int* in_sizes, int n_in,
                              void* d_out, int out_size)
{
    const float* hid  = (const float*)d_in[0];   // [B,H]
    const float* enc  = (const float*)d_in[1];   // [B,S,H]
    const void*  mask = d_in[2];                 // [B,S] bool (width detected)

    float* ctx     = (float*)d_out;            // [B,H]
    float* weights = (float*)d_out + B_ * H_;  // [B,S]

    static bool attr_set = false;
    if (!attr_set) {
        cudaFuncSetAttribute(k1_scores_partials,
                             cudaFuncAttributeMaxDynamicSharedMemorySize,
                             SMEM_TOTAL);
        attr_set = true;
    }

    k1_scores_partials<<<NBLOCKS1, 256, SMEM_TOTAL>>>(hid, enc, mask, weights);
    k2_fused<<<dim3(5, B_), 256>>>(ctx, (float4*)weights);
}

// round 7
// speedup vs baseline: 3.6862x; 1.0675x over previous
#include <cuda_runtime.h>
#include <math.h>

// Problem constants (fixed by the reference)
#define B_  64
#define S_  8192
#define H_  512
#define STILE 512
#define NTILES (S_ / STILE)    // 16
#define NBLOCKS1 (B_ * NTILES) // 1024

// Scratch (allocation-free: __device__ globals)
__device__ float g_partial[B_ * NTILES * H_];  // 2 MB
__device__ float g_m[B_ * NTILES];
__device__ float g_l[B_ * NTILES];

// Dynamic smem layout (bytes). sm_ctx (16 KB) is ALIASED into the stage
// region: it is only touched after the main loop, past a __syncthreads(),
// when all cp.async traffic has drained.
#define OFF_HID     0                         // 2048  (128 float4)
#define OFF_SCORES  2048                      // 2048  (8 x 64 floats)
#define OFF_ROWS    4096                      // 512   (8 x 64 bytes)
#define OFF_M       4608                      // 32
#define OFF_L       4640                      // 32
#define OFF_FLAG    4672                      // 32
#define OFF_STAGE   4736                      // 128-aligned
#define STAGE_PER_WARP 12288                  // 3 bufs x 2 rows x 2048 B
#define SMEM_TOTAL  (OFF_STAGE + 8 * STAGE_PER_WARP)  // 103040 B (~100.6 KB)

// ---------------------------------------------------------------------------
// Kernel 1: one block per (batch, 512-row S-tile). Each warp owns 64 rows.
// Active rows compacted into a smem list (ballot+popc). Main loop walks the
// list 2 rows per group with a TRIPLE-BUFFERED cp.async pipeline: groups g+1
// and g+2 stream HBM->smem while group g is computed from smem.
// ---------------------------------------------------------------------------
__global__ __launch_bounds__(256)
void k1_scores_partials(const float* __restrict__ hid,
                        const float* __restrict__ enc,
                        const void* __restrict__ mask,
                        float* __restrict__ scores_out /* = d_out + B*H */)
{
    extern __shared__ char dsm[];
    float4*        sh_hid    = (float4*)(dsm + OFF_HID);
    float*         sm_scores = (float*)(dsm + OFF_SCORES);
    unsigned char* sm_rows   = (unsigned char*)(dsm + OFF_ROWS);
    float*         sm_m      = (float*)(dsm + OFF_M);
    float*         sm_l      = (float*)(dsm + OFF_L);
    int*           sh_flag   = (int*)(dsm + OFF_FLAG);
    float*         sm_ctx    = (float*)(dsm + OFF_STAGE);   // ALIASED w/ stage

    const int b = blockIdx.x / NTILES;
    const int t = blockIdx.x % NTILES;
    const int tid  = threadIdx.x;
    const int warp = tid >> 5;
    const int lane = tid & 31;

    // decoder_hidden[b,:] -> smem
    {
        const float4* h4 = (const float4*)(hid + (size_t)b * H_);
        if (tid < H_ / 4) sh_hid[tid] = h4[tid];
    }
    sm_scores[warp * 64 + lane]      = -INFINITY;
    sm_scores[warp * 64 + lane + 32] = -INFINITY;

    // mask width detection: branch-free OR over first 512 words (safe under
    // both layouts; byte-bools give a word>1 with prob 1-(1/8)^512 ~ 1)
    {
        const unsigned int* mw = (const unsigned int*)mask;
        unsigned int v = mw[tid] | mw[tid + 256];
        unsigned any = __any_sync(0xffffffffu, v > 1u);
        if (lane == 0) sh_flag[warp] = any ? 1 : 0;
    }
    __syncthreads();
    const int mask_is_byte = sh_flag[0] | sh_flag[1] | sh_flag[2] | sh_flag[3]
                           | sh_flag[4] | sh_flag[5] | sh_flag[6] | sh_flag[7];

    float4 hv[4];
#pragma unroll
    for (int j = 0; j < 4; ++j) hv[j] = sh_hid[lane + 32 * j];

    // this warp's 64 rows: ballots + parallel compaction into sm_rows
    const int row0 = t * STILE + warp * 64;
    bool k0b, k1b;
    if (mask_is_byte) {
        const unsigned char* mp = (const unsigned char*)mask + (size_t)b * S_ + row0;
        k0b = mp[lane] != 0;  k1b = mp[lane + 32] != 0;
    } else {
        const int* mp = (const int*)mask + (size_t)b * S_ + row0;
        k0b = mp[lane] != 0;  k1b = mp[lane + 32] != 0;
    }
    const unsigned b0 = __ballot_sync(0xffffffffu, k0b);
    const unsigned b1 = __ballot_sync(0xffffffffu, k1b);
    const unsigned lmask = (lane == 31) ? 0x7fffffffu : ((1u << lane) - 1u);
    if (k0b) sm_rows[warp * 64 + __popc(b0 & lmask)] = (unsigned char)lane;
    if (k1b) sm_rows[warp * 64 + __popc(b0) + __popc(b1 & lmask)] = (unsigned char)(lane + 32);
    const int cnt = __popc(b0) + __popc(b1);
    __syncwarp();

    const char* gbase = (const char*)(enc + ((size_t)b * S_ + row0) * H_);
    char* stage = dsm + OFF_STAGE + warp * STAGE_PER_WARP;

    float acc[16];
#pragma unroll
    for (int k = 0; k < 16; ++k) acc[k] = 0.f;
    float m = -INFINITY, l = 0.f;

    const int ngroups = (cnt + 1) >> 1;

    // stage group g into buffer g%3 (2 rows x 2 KB)
    auto issue_group = [&](int g) {
        const int i0 = 2 * g;
        const int r0 = sm_rows[warp * 64 + i0];
        const int r1 = (i0 + 1 < cnt) ? sm_rows[warp * 64 + i0 + 1] : r0;
        char* buf = stage + (g % 3) * 4096;
        unsigned int s0 = (unsigned int)__cvta_generic_to_shared(buf) + lane * 16;
        const char* g0 = gbase + (size_t)r0 * 2048 + lane * 16;
        const char* g1 = gbase + (size_t)r1 * 2048 + lane * 16;
#pragma unroll
        for (int j = 0; j < 4; ++j) {
            asm volatile("cp.async.cg.shared.global [%0], [%1], 16;"
                         :: "r"(s0 + j * 512), "l"(g0 + j * 512));
            asm volatile("cp.async.cg.shared.global [%0], [%1], 16;"
                         :: "r"(s0 + 2048 + j * 512), "l"(g1 + j * 512));
        }
        asm volatile("cp.async.commit_group;" ::: "memory");
    };

    if (ngroups > 0) {
        issue_group(0);
        if (ngroups > 1) issue_group(1);

        for (int g = 0; g < ngroups; ++g) {
            if (g + 2 < ngroups) {
                issue_group(g + 2);
                asm volatile("cp.async.wait_group 2;" ::: "memory");
            } else if (g + 1 < ngroups) {
                asm volatile("cp.async.wait_group 1;" ::: "memory");
            } else {
                asm volatile("cp.async.wait_group 0;" ::: "memory");
            }
            __syncwarp();   // staged bytes visible across lanes

            const int i0 = 2 * g;
            const int r0 = sm_rows[warp * 64 + i0];
            const bool v1 = (i0 + 1) < cnt;
            const int r1 = v1 ? sm_rows[warp * 64 + i0 + 1] : r0;

            const float4* buf = (const float4*)(stage + (g % 3) * 4096);
            float4 v[2][4];
#pragma unroll
            for (int j = 0; j < 4; ++j) {
                v[0][j] = buf[lane + 32 * j];
                v[1][j] = buf[128 + lane + 32 * j];
            }

            float p0, p1;
            {
                float s0 = v[0][0].x*hv[0].x + v[0][0].y*hv[0].y + v[0][0].z*hv[0].z + v[0][0].w*hv[0].w;
                float s1 = v[0][1].x*hv[1].x + v[0][1].y*hv[1].y + v[0][1].z*hv[1].z + v[0][1].w*hv[1].w;
                float s2 = v[0][2].x*hv[2].x + v[0][2].y*hv[2].y + v[0][2].z*hv[2].z + v[0][2].w*hv[2].w;
                float s3 = v[0][3].x*hv[3].x + v[0][3].y*hv[3].y + v[0][3].z*hv[3].z + v[0][3].w*hv[3].w;
                p0 = (s0 + s1) + (s2 + s3);
            }
            {
                float s0 = v[1][0].x*hv[0].x + v[1][0].y*hv[0].y + v[1][0].z*hv[0].z + v[1][0].w*hv[0].w;
                float s1 = v[1][1].x*hv[1].x + v[1][1].y*hv[1].y + v[1][1].z*hv[1].z + v[1][1].w*hv[1].w;
                float s2 = v[1][2].x*hv[2].x + v[1][2].y*hv[2].y + v[1][2].z*hv[2].z + v[1][2].w*hv[2].w;
                float s3 = v[1][3].x*hv[3].x + v[1][3].y*hv[3].y + v[1][3].z*hv[3].z + v[1][3].w*hv[3].w;
                p1 = (s0 + s1) + (s2 + s3);
            }
#pragma unroll
            for (int off = 16; off; off >>= 1) {
                p0 += __shfl_xor_sync(0xffffffffu, p0, off);
                p1 += __shfl_xor_sync(0xffffffffu, p1, off);
            }

            const float gmax = v1 ? fmaxf(p0, p1) : p0;
            if (gmax > m) {
                const float sc = __expf(m - gmax);  // exp(-inf - x) = 0 first time
                l *= sc;
#pragma unroll
                for (int k = 0; k < 16; ++k) acc[k] *= sc;
                m = gmax;
            }
            const float e0 = __expf(p0 - m);
            const float e1 = v1 ? __expf(p1 - m) : 0.f;
            l += e0 + e1;
#pragma unroll
            for (int j = 0; j < 4; ++j) {
                acc[4*j+0] += e0 * v[0][j].x + e1 * v[1][j].x;
                acc[4*j+1] += e0 * v[0][j].y + e1 * v[1][j].y;
                acc[4*j+2] += e0 * v[0][j].z + e1 * v[1][j].z;
                acc[4*j+3] += e0 * v[0][j].w + e1 * v[1][j].w;
            }
            if (lane == 0) {
                sm_scores[warp * 64 + r0] = p0;
                if (v1) sm_scores[warp * 64 + r1] = p1;
            }
        }
    }

    __syncwarp();
    // coalesced score stores
    scores_out[(size_t)b * S_ + row0 + lane]      = sm_scores[warp * 64 + lane];
    scores_out[(size_t)b * S_ + row0 + lane + 32] = sm_scores[warp * 64 + lane + 32];

    if (lane == 0) { sm_m[warp] = m; sm_l[warp] = l; }
    __syncthreads();   // all warps done with stage region -> sm_ctx alias safe

    // block max over the 8 warps
    float Mblk = -INFINITY;
#pragma unroll
    for (int w = 0; w < 8; ++w) Mblk = fmaxf(Mblk, sm_m[w]);

    // scale this warp's accumulator to the block max, dump to smem (float4)
    const float wscale = (m > -INFINITY) ? __expf(m - Mblk) : 0.f;
    float4* dst = (float4*)(sm_ctx + warp * H_);
#pragma unroll
    for (int j = 0; j < 4; ++j)
        dst[lane + 32 * j] = make_float4(acc[4*j+0] * wscale, acc[4*j+1] * wscale,
                                         acc[4*j+2] * wscale, acc[4*j+3] * wscale);
    __syncthreads();

    // reduce 8 warps -> per-tile partial context
    float* part = g_partial + (size_t)(b * NTILES + t) * H_;
    for (int h = tid; h < H_; h += 256) {
        float c = 0.f;
#pragma unroll
        for (int w = 0; w < 8; ++w) c += sm_ctx[w * H_ + h];
        part[h] = c;
    }

    if (tid == 0) {
        float L = 0.f;
#pragma unroll
        for (int w = 0; w < 8; ++w) {
            const float sc = (sm_m[w] > -INFINITY) ? __expf(sm_m[w] - Mblk) : 0.f;
            L += sm_l[w] * sc;
        }
        g_m[b * NTILES + t] = Mblk;
        g_l[b * NTILES + t] = L;
    }
}

// ---------------------------------------------------------------------------
// Per-batch (M, invT) from the tiny g_m/g_l arrays — warp 0, shfl reduce.
// ---------------------------------------------------------------------------
__device__ __forceinline__ void batch_stats(int b, int tid,
                                            float* sh_M, float* sh_invT)
{
    if (tid < 32) {
        float mt = (tid < NTILES) ? g_m[b * NTILES + tid] : -INFINITY;
        float lt = (tid < NTILES) ? g_l[b * NTILES + tid] : 0.f;
        float Mb = mt;
#pragma unroll
        for (int off = 16; off; off >>= 1)
            Mb = fmaxf(Mb, __shfl_xor_sync(0xffffffffu, Mb, off));
        float c = (mt > -INFINITY) ? lt * __expf(mt - Mb) : 0.f;
#pragma unroll
        for (int off = 16; off; off >>= 1)
            c += __shfl_xor_sync(0xffffffffu, c, off);
        if (tid == 0) { *sh_M = Mb; *sh_invT = 1.f / c; }
    }
    __syncthreads();
}

// ---------------------------------------------------------------------------
// Kernel 2 (fused tail): grid (5, 64). slice 0 -> context combine; slices
// 1..4 -> weights quarters. Streaming loads are PREFETCHED before the
// dependent batch_stats so the stats latency is hidden under them.
// ---------------------------------------------------------------------------
__global__ __launch_bounds__(256)
void k2_fused(float* __restrict__ ctx_out /* d_out */,
              float4* __restrict__ scores4 /* d_out + B*H */)
{
    const int slice = blockIdx.x;   // 0..4
    const int b     = blockIdx.y;
    const int tid   = threadIdx.x;

    __shared__ float sh_M, sh_invT;

    if (slice == 0) {
        // prefetch: 2 h-positions x 16 tiles of g_partial (32 independent loads)
        const int h0 = tid, h1 = tid + 256;
        float part0[NTILES], part1[NTILES];
#pragma unroll
        for (int t = 0; t < NTILES; ++t) {
            part0[t] = g_partial[(size_t)(b * NTILES + t) * H_ + h0];
            part1[t] = g_partial[(size_t)(b * NTILES + t) * H_ + h1];
        }
        __shared__ float sc[NTILES];
        batch_stats(b, tid, &sh_M, &sh_invT);
        if (tid < NTILES) {
            const float mt = g_m[b * NTILES + tid];
            sc[tid] = (mt > -INFINITY) ? __expf(mt - sh_M) : 0.f;
        }
        __syncthreads();
        const float iT = sh_invT;
        float c0 = 0.f, c1 = 0.f;
#pragma unroll
        for (int t = 0; t < NTILES; ++t) {
            c0 += part0[t] * sc[t];
            c1 += part1[t] * sc[t];
        }
        ctx_out[(size_t)b * H_ + h0] = c0 * iT;
        ctx_out[(size_t)b * H_ + h1] = c1 * iT;
    } else {
        // prefetch the 2 float4 per thread, then stats, then exp+store
        float4* p = scores4 + (size_t)b * (S_ / 4) + (slice - 1) * 512;
        float4 s0 = p[tid];
        float4 s1 = p[tid + 256];
        batch_stats(b, tid, &sh_M, &sh_invT);
        const float M  = sh_M;
        const float iT = sh_invT;
        s0.x = __expf(s0.x - M) * iT;  s0.y = __expf(s0.y - M) * iT;
        s0.z = __expf(s0.z - M) * iT;  s0.w = __expf(s0.w - M) * iT;
        s1.x = __expf(s1.x - M) * iT;  s1.y = __expf(s1.y - M) * iT;
        s1.z = __expf(s1.z - M) * iT;  s1.w = __expf(s1.w - M) * iT;
        p[tid]       = s0;
        p[tid + 256] = s1;
    }
}

// ---------------------------------------------------------------------------
extern "C" void kernel_launch(void* const* d_in, const int* in_sizes, int n_in,
                              void* d_out, int out_size)
{
    const float* hid  = (const float*)d_in[0];   // [B,H]
    const float* enc  = (const float*)d_in[1];   // [B,S,H]
    const void*  mask = d_in[2];                 // [B,S] bool (width detected)

    float* ctx     = (float*)d_out;            // [B,H]
    float* weights = (float*)d_out + B_ * H_;  // [B,S]

    static bool attr_set = false;
    if (!attr_set) {
        cudaFuncSetAttribute(k1_scores_partials,
                             cudaFuncAttributeMaxDynamicSharedMemorySize,
                             SMEM_TOTAL);
        attr_set = true;
    }

    k1_scores_partials<<<NBLOCKS1, 256, SMEM_TOTAL>>>(hid, enc, mask, weights);
    k2_fused<<<dim3(5, B_), 256>>>(ctx, (float4*)weights);
}